// round 8
// baseline (speedup 1.0000x reference)
#include <cuda_runtime.h>

// Problem constants
#define TD     64
#define MODES  16
#define MRI    32          // 2*MODES
#define PD     16384       // N*D pixels
#define SCOL   1048576     // PD*64 floats per time row
#define TILE_P 16
#define NBLK   (PD / TILE_P)   // 1024 CTAs
#define NTHR   256

#define TWO_PI_OVER_64 0.09817477042468103870f

typedef unsigned long long u64;

// Packed, transposed weights: g_W[m][c2][o] = ( (WR[2c2],WR[2c2+1]), (WI[2c2],WI[2c2+1]) )
__device__ ulonglong2 g_W[MODES * 32 * 64];   // 512 KB

// ---------- packed f32x2 helpers ----------
__device__ __forceinline__ u64 pack2(float a, float b) {
    u64 r;
    asm("mov.b64 %0, {%1, %2};" : "=l"(r) : "f"(a), "f"(b));
    return r;
}
__device__ __forceinline__ void unpack2(u64 v, float &lo, float &hi) {
    asm("mov.b64 {%0, %1}, %2;" : "=f"(lo), "=f"(hi) : "l"(v));
}
__device__ __forceinline__ void fma2(u64 &d, u64 a, u64 b) {
    asm("fma.rn.f32x2 %0, %1, %2, %0;" : "+l"(d) : "l"(a), "l"(b));
}
__device__ __forceinline__ u64 add2(u64 a, u64 b) {
    u64 r;
    asm("add.rn.f32x2 %0, %1, %2;" : "=l"(r) : "l"(a), "l"(b));
    return r;
}
__device__ __forceinline__ float hadd(u64 v) {
    float lo, hi;
    unpack2(v, lo, hi);
    return lo + hi;
}

// =====================================================================
// One-time weight repack: w[c][o][m][2]  ->  g_W[m][c2][o]
// =====================================================================
__global__ void __launch_bounds__(256) w_pack(const float* __restrict__ w) {
    int idx = blockIdx.x * 256 + threadIdx.x;     // 0 .. 32767
    int m  = idx >> 11;
    int c2 = (idx >> 6) & 31;
    int o  = idx & 63;
    int c0 = 2 * c2;
    const float* b0 = w + ((((c0    ) * 64 + o) * MODES + m) << 1);
    const float* b1 = w + ((((c0 + 1) * 64 + o) * MODES + m) << 1);
    ulonglong2 v;
    v.x = pack2(b0[0], b1[0]);
    v.y = pack2(b0[1], b1[1]);
    g_W[idx] = v;
}

// =====================================================================
// Fused spectral conv. 256 threads, 16 pixels per CTA, 224 KB smem.
// smem layout (bytes):
//   [0      , 16384 ) F2  [mri][t]   packed (f,f)
//   [16384  , 32768 ) G2  [t][mri]   packed (g,g)
//   [32768  ,163840 ) XY  [mri][16p][64c] f32  (128 KB) — X, overwritten
//                     in-place per mode by Y (mode m owns rows 2m,2m+1)
//   [163840 ,196608 ) W buf 0  [c2][o] ulonglong2
//   [196608 ,229376 ) W buf 1
// =====================================================================
__global__ void __launch_bounds__(NTHR, 1) fused_spectral(const float* __restrict__ x,
                                                          float* __restrict__ out) {
    extern __shared__ __align__(16) char smem[];
    u64*        F2   = reinterpret_cast<u64*>(smem);
    u64*        G2   = reinterpret_cast<u64*>(smem + 16384);
    u64*        XY64 = reinterpret_cast<u64*>(smem + 32768);
    float*      XYf  = reinterpret_cast<float*>(smem + 32768);
    ulonglong2* Wb0  = reinterpret_cast<ulonglong2*>(smem + 163840);
    ulonglong2* Wb1  = reinterpret_cast<ulonglong2*>(smem + 196608);

    const int tid = threadIdx.x;
    const int p0  = blockIdx.x * TILE_P;

    // ---- DFT tables ----
    for (int idx = tid; idx < MRI * TD; idx += NTHR) {      // F2[mri][t]
        int mri = idx >> 6, t = idx & 63, m = mri >> 1;
        float s, c;
        sincosf((float)((m * t) & 63) * TWO_PI_OVER_64, &s, &c);
        float v = (mri & 1) ? -s : c;
        F2[idx] = pack2(v, v);
    }
    for (int idx = tid; idx < TD * MRI; idx += NTHR) {      // G2[t][mri]
        int t = idx >> 5, mri = idx & 31, m = mri >> 1;
        float s, c;
        sincosf((float)((m * t) & 63) * TWO_PI_OVER_64, &s, &c);
        float alpha = ((m == 0) ? 1.0f : 2.0f) * (1.0f / 64.0f);
        float v = (mri & 1) ? (-alpha * s) : (alpha * c);
        G2[idx] = pack2(v, v);
    }

    // ---- prefetch W for mode 0 (overlaps with stage 1 gmem reads) ----
    ulonglong2 wreg[8];
#pragma unroll
    for (int k = 0; k < 8; k++) wreg[k] = g_W[tid + k * NTHR];

    __syncthreads();   // tables ready

    // =============== Stage 1: truncated rfft into smem ===============
    // 256 thr = 8 pixel-slots x 32 channel-pairs; 2 pixel passes.
    {
        const int cp = tid & 31;
        const int pp = tid >> 5;           // 0..7, warp-uniform

#pragma unroll
        for (int pass = 0; pass < 2; pass++) {
            const int p = pp + pass * 8;
            const u64* xp = reinterpret_cast<const u64*>(x) + (long)(p0 + p) * 32 + cp;

            u64 acc[MRI];
#pragma unroll
            for (int i = 0; i < MRI; i++) acc[i] = 0ull;

#pragma unroll 2
            for (int t = 0; t < TD; t += 2) {
                u64 xv0 = xp[(long)t * (SCOL / 2)];
                u64 xv1 = xp[(long)(t + 1) * (SCOL / 2)];
#pragma unroll
                for (int mri = 0; mri < MRI; mri++) {
                    ulonglong2 f = *reinterpret_cast<const ulonglong2*>(&F2[(mri << 6) + t]);
                    fma2(acc[mri], xv0, f.x);
                    fma2(acc[mri], xv1, f.y);
                }
            }
#pragma unroll
            for (int mri = 0; mri < MRI; mri++)
                XY64[(mri * TILE_P + p) * 32 + cp] = acc[mri];
        }
        // published at the first syncthreads inside the mode loop
    }

    // =============== Stage 2: per-mode complex channel mix ===============
    // 256 thr = 4 pixel-groups x 64 outputs; 4 pixels per thread.
    // In-place: mode m reads X rows 2m,2m+1 then overwrites them with Y.
    {
        const int o   = tid & 63;
        const int px0 = (tid >> 6) * 4;           // 0,4,8,12 warp-uniform

        for (int m = 0; m < MODES; m++) {
            ulonglong2* Wc = (m & 1) ? Wb1 : Wb0;
#pragma unroll
            for (int k = 0; k < 8; k++) Wc[tid + k * NTHR] = wreg[k];
            __syncthreads();   // W_m visible; also publishes Xsm (m=0) / Y_{m-1}

            if (m < MODES - 1) {
#pragma unroll
                for (int k = 0; k < 8; k++)
                    wreg[k] = g_W[(m + 1) * 2048 + tid + k * NTHR];
            }

            const u64* xR = XY64 + ((2 * m)     * TILE_P + px0) * 32;
            const u64* xI = XY64 + ((2 * m + 1) * TILE_P + px0) * 32;

            u64 aRR[4], aII[4], aRI[4], aIR[4];
#pragma unroll
            for (int q = 0; q < 4; q++) { aRR[q] = 0; aII[q] = 0; aRI[q] = 0; aIR[q] = 0; }

#pragma unroll 4
            for (int c2 = 0; c2 < 32; c2 += 2) {
                ulonglong2 wv0 = Wc[(c2 << 6) + o];          // LDS.128, conflict-free
                ulonglong2 wv1 = Wc[((c2 + 1) << 6) + o];    // LDS.128, conflict-free
#pragma unroll
                for (int q = 0; q < 4; q++) {
                    ulonglong2 xr = *reinterpret_cast<const ulonglong2*>(&xR[q * 32 + c2]); // bcast
                    ulonglong2 xi = *reinterpret_cast<const ulonglong2*>(&xI[q * 32 + c2]); // bcast
                    fma2(aRR[q], xr.x, wv0.x); fma2(aII[q], xi.x, wv0.y);
                    fma2(aRI[q], xr.x, wv0.y); fma2(aIR[q], xi.x, wv0.x);
                    fma2(aRR[q], xr.y, wv1.x); fma2(aII[q], xi.y, wv1.y);
                    fma2(aRI[q], xr.y, wv1.y); fma2(aIR[q], xi.y, wv1.x);
                }
            }

            __syncthreads();   // all reads of X_m complete before overwrite

#pragma unroll
            for (int q = 0; q < 4; q++) {
                float yr = hadd(aRR[q]) - hadd(aII[q]);
                float yi = hadd(aRI[q]) + hadd(aIR[q]);
                XYf[((2 * m)     * TILE_P + px0 + q) * 64 + o] = yr;
                XYf[((2 * m + 1) * TILE_P + px0 + q) * 64 + o] = yi;
            }
        }
    }
    __syncthreads();   // Y complete

    // =============== Stage 3: truncated irfft from smem ===============
    // 256 thr = 8 pixel-slots x 32 output-pairs; 2 pixel passes.
    {
        const int op = tid & 31;
        const int pp = tid >> 5;

#pragma unroll
        for (int pass = 0; pass < 2; pass++) {
            const int p = pp + pass * 8;

            u64 y2[MRI];
#pragma unroll
            for (int mri = 0; mri < MRI; mri++)
                y2[mri] = XY64[(mri * TILE_P + p) * 32 + op];

            u64* outp = reinterpret_cast<u64*>(out) + (long)(p0 + p) * 32 + op;
#pragma unroll 2
            for (int t = 0; t < TD; t++) {
                u64 a0 = 0, a1 = 0, a2 = 0, a3 = 0;   // 4 independent chains
#pragma unroll
                for (int q = 0; q < 4; q++) {
                    ulonglong2 gA = *reinterpret_cast<const ulonglong2*>(&G2[(t << 5) + 8 * q]);
                    ulonglong2 gB = *reinterpret_cast<const ulonglong2*>(&G2[(t << 5) + 8 * q + 2]);
                    ulonglong2 gC = *reinterpret_cast<const ulonglong2*>(&G2[(t << 5) + 8 * q + 4]);
                    ulonglong2 gD = *reinterpret_cast<const ulonglong2*>(&G2[(t << 5) + 8 * q + 6]);
                    fma2(a0, y2[8 * q],     gA.x);
                    fma2(a0, y2[8 * q + 1], gA.y);
                    fma2(a1, y2[8 * q + 2], gB.x);
                    fma2(a1, y2[8 * q + 3], gB.y);
                    fma2(a2, y2[8 * q + 4], gC.x);
                    fma2(a2, y2[8 * q + 5], gC.y);
                    fma2(a3, y2[8 * q + 6], gD.x);
                    fma2(a3, y2[8 * q + 7], gD.y);
                }
                outp[(long)t * (SCOL / 2)] = add2(add2(a0, a1), add2(a2, a3));
            }
        }
    }
}

// =====================================================================
extern "C" void kernel_launch(void* const* d_in, const int* in_sizes, int n_in,
                              void* d_out, int out_size) {
    const float* x = (const float*)d_in[0];   // [64][1024][16][64] f32
    const float* w = (const float*)d_in[1];   // [64][64][16][2] f32
    float* out     = (float*)d_out;           // [64][1024][16][64] f32
    (void)in_sizes; (void)n_in; (void)out_size;

    cudaFuncSetAttribute(fused_spectral, cudaFuncAttributeMaxDynamicSharedMemorySize, 229376);

    w_pack<<<128, 256>>>(w);
    fused_spectral<<<NBLK, NTHR, 229376>>>(x, out);
}

// round 9
// speedup vs baseline: 1.4641x; 1.4641x over previous
#include <cuda_runtime.h>

// Problem constants
#define TD     64
#define MODES  16
#define MRI    32          // 2*MODES
#define PD     16384       // N*D pixels
#define SCOL   1048576     // PD*64 floats per time row
#define TILE_P 16
#define NBLK   (PD / TILE_P)   // 1024 CTAs
#define NTHR   256

typedef unsigned long long u64;

// Packed, transposed weights: g_W[m][c2][o] = ( (WR[2c2],WR[2c2+1]), (WI[2c2],WI[2c2+1]) )
__device__ ulonglong2 g_W[MODES * 32 * 64];   // 512 KB

// ---------- compile-time DFT coefficients ----------
// cos(2*pi*k/64), folded to FFMA immediates after full unroll.
__host__ __device__ constexpr float cos64(int k) {
    constexpr float COSQ[17] = {
        1.0f,
        0.995184726672197f, 0.980785280403230f, 0.956940335732209f,
        0.923879532511287f, 0.881921264348355f, 0.831469612302545f,
        0.773010453362737f, 0.707106781186548f, 0.634393284163645f,
        0.555570233019602f, 0.471396736825998f, 0.382683432365090f,
        0.290284677254462f, 0.195090322016128f, 0.098017140329561f,
        0.0f
    };
    k &= 63;
    float s = 1.0f;
    if (k > 32) k = 64 - k;
    if (k > 16) { k = 32 - k; s = -1.0f; }
    return s * COSQ[k];
}
// Stage-1 coefficient: F[2m][t]=cos, F[2m+1][t]=-sin = cos(theta + pi/2)
__host__ __device__ constexpr float fconst(int mri, int t) {
    int m = mri >> 1;
    return (mri & 1) ? cos64(m * t + 16) : cos64(m * t);
}
// Stage-3 coefficient: G[t][2m]=a*cos, G[t][2m+1]=-a*sin; a=(m?2:1)/64
__host__ __device__ constexpr float gconst(int t, int mri) {
    int m = mri >> 1;
    float a = ((m == 0) ? 1.0f : 2.0f) / 64.0f;
    return a * ((mri & 1) ? cos64(m * t + 16) : cos64(m * t));
}

// ---------- packed f32x2 helpers ----------
__device__ __forceinline__ u64 pack2(float a, float b) {
    u64 r;
    asm("mov.b64 %0, {%1, %2};" : "=l"(r) : "f"(a), "f"(b));
    return r;
}
__device__ __forceinline__ void unpack2(u64 v, float &lo, float &hi) {
    asm("mov.b64 {%0, %1}, %2;" : "=f"(lo), "=f"(hi) : "l"(v));
}
__device__ __forceinline__ void fma2(u64 &d, u64 a, u64 b) {
    asm("fma.rn.f32x2 %0, %1, %2, %0;" : "+l"(d) : "l"(a), "l"(b));
}
__device__ __forceinline__ float hadd(u64 v) {
    float lo, hi;
    unpack2(v, lo, hi);
    return lo + hi;
}

// =====================================================================
// One-time weight repack: w[c][o][m][2]  ->  g_W[m][c2][o]
// =====================================================================
__global__ void __launch_bounds__(256) w_pack(const float* __restrict__ w) {
    int idx = blockIdx.x * 256 + threadIdx.x;     // 0 .. 32767
    int m  = idx >> 11;
    int c2 = (idx >> 6) & 31;
    int o  = idx & 63;
    int c0 = 2 * c2;
    const float* b0 = w + ((((c0    ) * 64 + o) * MODES + m) << 1);
    const float* b1 = w + ((((c0 + 1) * 64 + o) * MODES + m) << 1);
    ulonglong2 v;
    v.x = pack2(b0[0], b1[0]);
    v.y = pack2(b0[1], b1[1]);
    g_W[idx] = v;
}

// =====================================================================
// Fused spectral conv. 256 threads, 16 pixels per CTA, 192 KB smem.
// smem layout (bytes):
//   [0      ,131072 ) XY  [mri][16p][64c] f32 — X, overwritten in-place
//                     per mode by Y (mode m owns rows 2m,2m+1)
//   [131072 ,163840 ) W buf 0  [c2][o] ulonglong2
//   [163840 ,196608 ) W buf 1
// Stages 1 & 3 use compile-time FFMA-imm coefficients (no tables).
// =====================================================================
__global__ void __launch_bounds__(NTHR, 1) fused_spectral(const float* __restrict__ x,
                                                          float* __restrict__ out) {
    extern __shared__ __align__(16) char smem[];
    u64*        XY64 = reinterpret_cast<u64*>(smem);
    float*      XYf  = reinterpret_cast<float*>(smem);
    ulonglong2* Wb0  = reinterpret_cast<ulonglong2*>(smem + 131072);
    ulonglong2* Wb1  = reinterpret_cast<ulonglong2*>(smem + 163840);

    const int tid = threadIdx.x;
    const int p0  = blockIdx.x * TILE_P;

    // ---- prefetch W for mode 0 (overlaps with stage 1 gmem reads) ----
    ulonglong2 wreg[8];
#pragma unroll
    for (int k = 0; k < 8; k++) wreg[k] = g_W[tid + k * NTHR];

    // =============== Stage 1: truncated rfft into smem ===============
    // 256 thr = 8 pixel-slots x 32 channel-pairs; 2 pixel passes.
    // Coefficients are FFMA immediates (compile-time); exact zeros skipped.
    {
        const int cp = tid & 31;
        const int pp = tid >> 5;           // 0..7, warp-uniform

        for (int pass = 0; pass < 2; pass++) {
            const int p = pp + pass * 8;
            const u64* xp = reinterpret_cast<const u64*>(x) + (long)(p0 + p) * 32 + cp;

            float a0[MRI], a1[MRI];
#pragma unroll
            for (int i = 0; i < MRI; i++) { a0[i] = 0.0f; a1[i] = 0.0f; }

#pragma unroll
            for (int t = 0; t < TD; t++) {
                u64 xv = xp[(long)t * (SCOL / 2)];
                float x0, x1;
                unpack2(xv, x0, x1);
#pragma unroll
                for (int mri = 0; mri < MRI; mri++) {
                    const float f = fconst(mri, t);
                    if (f != 0.0f) {
                        a0[mri] = fmaf(x0, f, a0[mri]);
                        a1[mri] = fmaf(x1, f, a1[mri]);
                    }
                }
            }
#pragma unroll
            for (int mri = 0; mri < MRI; mri++)
                XY64[(mri * TILE_P + p) * 32 + cp] = pack2(a0[mri], a1[mri]);
        }
        // published at the first syncthreads inside the mode loop
    }

    // =============== Stage 2: per-mode complex channel mix ===============
    // 256 thr = 4 pixel-groups x 64 outputs; 4 pixels per thread.
    // In-place: mode m reads X rows 2m,2m+1 then overwrites them with Y.
    {
        const int o   = tid & 63;
        const int px0 = (tid >> 6) * 4;           // 0,4,8,12 warp-uniform

        for (int m = 0; m < MODES; m++) {
            ulonglong2* Wc = (m & 1) ? Wb1 : Wb0;
#pragma unroll
            for (int k = 0; k < 8; k++) Wc[tid + k * NTHR] = wreg[k];
            __syncthreads();   // W_m visible; also publishes Xsm (m=0) / Y_{m-1}

            if (m < MODES - 1) {
#pragma unroll
                for (int k = 0; k < 8; k++)
                    wreg[k] = g_W[(m + 1) * 2048 + tid + k * NTHR];
            }

            const u64* xR = XY64 + ((2 * m)     * TILE_P + px0) * 32;
            const u64* xI = XY64 + ((2 * m + 1) * TILE_P + px0) * 32;

            u64 aRR[4], aII[4], aRI[4], aIR[4];
#pragma unroll
            for (int q = 0; q < 4; q++) { aRR[q] = 0; aII[q] = 0; aRI[q] = 0; aIR[q] = 0; }

#pragma unroll 4
            for (int c2 = 0; c2 < 32; c2 += 2) {
                ulonglong2 wv0 = Wc[(c2 << 6) + o];          // LDS.128, conflict-free
                ulonglong2 wv1 = Wc[((c2 + 1) << 6) + o];    // LDS.128, conflict-free
#pragma unroll
                for (int q = 0; q < 4; q++) {
                    ulonglong2 xr = *reinterpret_cast<const ulonglong2*>(&xR[q * 32 + c2]); // bcast
                    ulonglong2 xi = *reinterpret_cast<const ulonglong2*>(&xI[q * 32 + c2]); // bcast
                    fma2(aRR[q], xr.x, wv0.x); fma2(aII[q], xi.x, wv0.y);
                    fma2(aRI[q], xr.x, wv0.y); fma2(aIR[q], xi.x, wv0.x);
                    fma2(aRR[q], xr.y, wv1.x); fma2(aII[q], xi.y, wv1.y);
                    fma2(aRI[q], xr.y, wv1.y); fma2(aIR[q], xi.y, wv1.x);
                }
            }

            __syncthreads();   // all reads of X_m complete before overwrite

#pragma unroll
            for (int q = 0; q < 4; q++) {
                float yr = hadd(aRR[q]) - hadd(aII[q]);
                float yi = hadd(aRI[q]) + hadd(aIR[q]);
                XYf[((2 * m)     * TILE_P + px0 + q) * 64 + o] = yr;
                XYf[((2 * m + 1) * TILE_P + px0 + q) * 64 + o] = yi;
            }
        }
    }
    __syncthreads();   // Y complete

    // =============== Stage 3: truncated irfft from smem ===============
    // 256 thr = 8 pixel-slots x 32 output-pairs; 2 pixel passes.
    // Coefficients are FFMA immediates; two chains per output for ILP.
    {
        const int op = tid & 31;
        const int pp = tid >> 5;

        for (int pass = 0; pass < 2; pass++) {
            const int p = pp + pass * 8;

            float y0[MRI], y1[MRI];
#pragma unroll
            for (int mri = 0; mri < MRI; mri++) {
                u64 v = XY64[(mri * TILE_P + p) * 32 + op];
                unpack2(v, y0[mri], y1[mri]);
            }

            u64* outp = reinterpret_cast<u64*>(out) + (long)(p0 + p) * 32 + op;
#pragma unroll
            for (int t = 0; t < TD; t++) {
                float s0a = 0.0f, s0b = 0.0f, s1a = 0.0f, s1b = 0.0f;
#pragma unroll
                for (int mri = 0; mri < MRI; mri++) {
                    const float g = gconst(t, mri);
                    if (g != 0.0f) {
                        if (mri & 1) {
                            s0b = fmaf(y0[mri], g, s0b);
                            s1b = fmaf(y1[mri], g, s1b);
                        } else {
                            s0a = fmaf(y0[mri], g, s0a);
                            s1a = fmaf(y1[mri], g, s1a);
                        }
                    }
                }
                outp[(long)t * (SCOL / 2)] = pack2(s0a + s0b, s1a + s1b);
            }
        }
    }
}

// =====================================================================
extern "C" void kernel_launch(void* const* d_in, const int* in_sizes, int n_in,
                              void* d_out, int out_size) {
    const float* x = (const float*)d_in[0];   // [64][1024][16][64] f32
    const float* w = (const float*)d_in[1];   // [64][64][16][2] f32
    float* out     = (float*)d_out;           // [64][1024][16][64] f32
    (void)in_sizes; (void)n_in; (void)out_size;

    cudaFuncSetAttribute(fused_spectral, cudaFuncAttributeMaxDynamicSharedMemorySize, 196608);

    w_pack<<<128, 256>>>(w);
    fused_spectral<<<NBLK, NTHR, 196608>>>(x, out);
}

// round 10
// speedup vs baseline: 1.5763x; 1.0766x over previous
#include <cuda_runtime.h>

// Problem constants
#define TD     64
#define MODES  16
#define MRI    32          // 2*MODES
#define PD     16384       // N*D pixels
#define SCOL   1048576     // PD*64 floats per time row
#define TILE_P 16
#define NBLK   (PD / TILE_P)   // 1024 CTAs
#define NTHR   256

typedef unsigned long long u64;

// Packed, transposed weights: g_W[m][c2][o] = ( (WR[2c2],WR[2c2+1]), (WI[2c2],WI[2c2+1]) )
__device__ ulonglong2 g_W[MODES * 32 * 64];   // 512 KB

// ---------- compile-time DFT coefficients ----------
// cos(2*pi*k/64); folded into FFMA immediates after full unroll.
__host__ __device__ constexpr float cos64(int k) {
    constexpr float COSQ[17] = {
        1.0f,
        0.995184726672197f, 0.980785280403230f, 0.956940335732209f,
        0.923879532511287f, 0.881921264348355f, 0.831469612302545f,
        0.773010453362737f, 0.707106781186548f, 0.634393284163645f,
        0.555570233019602f, 0.471396736825998f, 0.382683432365090f,
        0.290284677254462f, 0.195090322016128f, 0.098017140329561f,
        0.0f
    };
    k &= 63;
    float s = 1.0f;
    if (k > 32) k = 64 - k;
    if (k > 16) { k = 32 - k; s = -1.0f; }
    return s * COSQ[k];
}
// irfft row scale: alpha_m / 64
__host__ __device__ constexpr float alpha64(int m) {
    return ((m == 0) ? 1.0f : 2.0f) / 64.0f;
}

// ---------- packed f32x2 helpers ----------
__device__ __forceinline__ u64 pack2(float a, float b) {
    u64 r;
    asm("mov.b64 %0, {%1, %2};" : "=l"(r) : "f"(a), "f"(b));
    return r;
}
__device__ __forceinline__ void unpack2(u64 v, float &lo, float &hi) {
    asm("mov.b64 {%0, %1}, %2;" : "=f"(lo), "=f"(hi) : "l"(v));
}
__device__ __forceinline__ void fma2(u64 &d, u64 a, u64 b) {
    asm("fma.rn.f32x2 %0, %1, %2, %0;" : "+l"(d) : "l"(a), "l"(b));
}
__device__ __forceinline__ float hadd(u64 v) {
    float lo, hi;
    unpack2(v, lo, hi);
    return lo + hi;
}

// =====================================================================
// One-time weight repack: w[c][o][m][2]  ->  g_W[m][c2][o]
// =====================================================================
__global__ void __launch_bounds__(256) w_pack(const float* __restrict__ w) {
    int idx = blockIdx.x * 256 + threadIdx.x;     // 0 .. 32767
    int m  = idx >> 11;
    int c2 = (idx >> 6) & 31;
    int o  = idx & 63;
    int c0 = 2 * c2;
    const float* b0 = w + ((((c0    ) * 64 + o) * MODES + m) << 1);
    const float* b1 = w + ((((c0 + 1) * 64 + o) * MODES + m) << 1);
    ulonglong2 v;
    v.x = pack2(b0[0], b1[0]);
    v.y = pack2(b0[1], b1[1]);
    g_W[idx] = v;
}

// =====================================================================
// Fused spectral conv. 256 threads, 16 pixels per CTA, 192 KB smem.
// smem layout (bytes):
//   [0      ,131072 ) XY  [mri][16p][64c] f32 — X, overwritten in-place
//                     per mode by Y (mode m owns rows 2m,2m+1)
//   [131072 ,163840 ) W buf 0  [c2][o] ulonglong2
//   [163840 ,196608 ) W buf 1
// Stages 1 & 3 use compile-time FFMA-imm coefficients with t<->64-t
// symmetry folding (half the FMAs of the unfolded form).
// =====================================================================
__global__ void __launch_bounds__(NTHR, 1) fused_spectral(const float* __restrict__ x,
                                                          float* __restrict__ out) {
    extern __shared__ __align__(16) char smem[];
    u64*        XY64 = reinterpret_cast<u64*>(smem);
    float*      XYf  = reinterpret_cast<float*>(smem);
    ulonglong2* Wb0  = reinterpret_cast<ulonglong2*>(smem + 131072);
    ulonglong2* Wb1  = reinterpret_cast<ulonglong2*>(smem + 163840);

    const int tid = threadIdx.x;
    const int p0  = blockIdx.x * TILE_P;

    // ---- prefetch W for mode 0 (overlaps with stage 1 gmem reads) ----
    ulonglong2 wreg[8];
#pragma unroll
    for (int k = 0; k < 8; k++) wreg[k] = g_W[tid + k * NTHR];

    // =============== Stage 1: truncated rfft into smem (folded) ===============
    // Xc[m] = x0 + (-1)^m x32 + sum_{t=1..31} cos64(mt) * (x[t]+x[64-t])
    // Xs[m] = sum_{t=1..31} cos64(mt+16) * (x[t]-x[64-t])    (= -sin row; 0 for m=0)
    {
        const int cp = tid & 31;
        const int pp = tid >> 5;           // 0..7, warp-uniform

        for (int pass = 0; pass < 2; pass++) {
            const int p = pp + pass * 8;
            const u64* xp = reinterpret_cast<const u64*>(x) + (long)(p0 + p) * 32 + cp;

            float XcL[16], XcH[16], XsL[16], XsH[16];
            {
                float x0L, x0H, x32L, x32H;
                unpack2(xp[0], x0L, x0H);
                unpack2(xp[32 * (SCOL / 2)], x32L, x32H);
#pragma unroll
                for (int m = 0; m < 16; m++) {
                    if (m & 1) { XcL[m] = x0L - x32L; XcH[m] = x0H - x32H; }
                    else       { XcL[m] = x0L + x32L; XcH[m] = x0H + x32H; }
                    XsL[m] = 0.0f; XsH[m] = 0.0f;
                }
            }

#pragma unroll
            for (int t = 1; t < 32; t++) {
                float aL, aH, bL, bH;
                unpack2(xp[(long)t * (SCOL / 2)], aL, aH);
                unpack2(xp[(long)(64 - t) * (SCOL / 2)], bL, bH);
                const float eL = aL + bL, eH = aH + bH;
                const float oL = aL - bL, oH = aH - bH;
                XcL[0] += eL; XcH[0] += eH;          // m=0 cos row (coeff 1)
#pragma unroll
                for (int m = 1; m < 16; m++) {
                    const float fc = cos64(m * t);          // cos coeff
                    const float fs = cos64(m * t + 16);     // -sin coeff
                    if (fc != 0.0f) {
                        XcL[m] = fmaf(eL, fc, XcL[m]);
                        XcH[m] = fmaf(eH, fc, XcH[m]);
                    }
                    if (fs != 0.0f) {
                        XsL[m] = fmaf(oL, fs, XsL[m]);
                        XsH[m] = fmaf(oH, fs, XsH[m]);
                    }
                }
            }

#pragma unroll
            for (int m = 0; m < 16; m++) {
                XY64[((2 * m)     * TILE_P + p) * 32 + cp] = pack2(XcL[m], XcH[m]);
                XY64[((2 * m + 1) * TILE_P + p) * 32 + cp] = pack2(XsL[m], XsH[m]);
            }
        }
        // published at the first syncthreads inside the mode loop
    }

    // =============== Stage 2: per-mode complex channel mix ===============
    // 256 thr = 4 pixel-groups x 64 outputs; 4 pixels per thread.
    // In-place: mode m reads X rows 2m,2m+1 then overwrites them with Y.
    {
        const int o   = tid & 63;
        const int px0 = (tid >> 6) * 4;           // 0,4,8,12 warp-uniform

        for (int m = 0; m < MODES; m++) {
            ulonglong2* Wc = (m & 1) ? Wb1 : Wb0;
#pragma unroll
            for (int k = 0; k < 8; k++) Wc[tid + k * NTHR] = wreg[k];
            __syncthreads();   // W_m visible; also publishes Xsm (m=0) / Y_{m-1}

            if (m < MODES - 1) {
#pragma unroll
                for (int k = 0; k < 8; k++)
                    wreg[k] = g_W[(m + 1) * 2048 + tid + k * NTHR];
            }

            const u64* xR = XY64 + ((2 * m)     * TILE_P + px0) * 32;
            const u64* xI = XY64 + ((2 * m + 1) * TILE_P + px0) * 32;

            u64 aRR[4], aII[4], aRI[4], aIR[4];
#pragma unroll
            for (int q = 0; q < 4; q++) { aRR[q] = 0; aII[q] = 0; aRI[q] = 0; aIR[q] = 0; }

#pragma unroll 4
            for (int c2 = 0; c2 < 32; c2 += 2) {
                ulonglong2 wv0 = Wc[(c2 << 6) + o];          // LDS.128, conflict-free
                ulonglong2 wv1 = Wc[((c2 + 1) << 6) + o];    // LDS.128, conflict-free
#pragma unroll
                for (int q = 0; q < 4; q++) {
                    ulonglong2 xr = *reinterpret_cast<const ulonglong2*>(&xR[q * 32 + c2]); // bcast
                    ulonglong2 xi = *reinterpret_cast<const ulonglong2*>(&xI[q * 32 + c2]); // bcast
                    fma2(aRR[q], xr.x, wv0.x); fma2(aII[q], xi.x, wv0.y);
                    fma2(aRI[q], xr.x, wv0.y); fma2(aIR[q], xi.x, wv0.x);
                    fma2(aRR[q], xr.y, wv1.x); fma2(aII[q], xi.y, wv1.y);
                    fma2(aRI[q], xr.y, wv1.y); fma2(aIR[q], xi.y, wv1.x);
                }
            }

            __syncthreads();   // all reads of X_m complete before overwrite

#pragma unroll
            for (int q = 0; q < 4; q++) {
                float yr = hadd(aRR[q]) - hadd(aII[q]);
                float yi = hadd(aRI[q]) + hadd(aIR[q]);
                XYf[((2 * m)     * TILE_P + px0 + q) * 64 + o] = yr;
                XYf[((2 * m + 1) * TILE_P + px0 + q) * 64 + o] = yi;
            }
        }
    }
    __syncthreads();   // Y complete

    // =============== Stage 3: truncated irfft from smem (folded) ===============
    // C[t] = sum_m alpha64(m)*cos64(mt)   * YR[m]
    // S[t] = sum_m alpha64(m)*cos64(mt+16)* YI[m]     (= -alpha*sin)
    // out[t] = C+S, out[64-t] = C-S; t=0,32 are C-only.
    {
        const int op = tid & 31;
        const int pp = tid >> 5;

        for (int pass = 0; pass < 2; pass++) {
            const int p = pp + pass * 8;

            float yRL[16], yRH[16], yIL[16], yIH[16];
#pragma unroll
            for (int m = 0; m < 16; m++) {
                unpack2(XY64[((2 * m)     * TILE_P + p) * 32 + op], yRL[m], yRH[m]);
                unpack2(XY64[((2 * m + 1) * TILE_P + p) * 32 + op], yIL[m], yIH[m]);
            }

            u64* outp = reinterpret_cast<u64*>(out) + (long)(p0 + p) * 32 + op;

            // t = 0 : sum alpha*YR
            {
                float c0 = 0.0f, c1 = 0.0f;
#pragma unroll
                for (int m = 0; m < 16; m++) {
                    const float g = alpha64(m);
                    c0 = fmaf(yRL[m], g, c0);
                    c1 = fmaf(yRH[m], g, c1);
                }
                outp[0] = pack2(c0, c1);
            }
            // t = 32 : sum alpha*(-1)^m*YR
            {
                float c0 = 0.0f, c1 = 0.0f;
#pragma unroll
                for (int m = 0; m < 16; m++) {
                    const float g = (m & 1) ? -alpha64(m) : alpha64(m);
                    c0 = fmaf(yRL[m], g, c0);
                    c1 = fmaf(yRH[m], g, c1);
                }
                outp[32 * (SCOL / 2)] = pack2(c0, c1);
            }

#pragma unroll
            for (int t = 1; t < 32; t++) {
                float C0 = 0.0f, C1 = 0.0f, S0 = 0.0f, S1 = 0.0f;
#pragma unroll
                for (int m = 0; m < 16; m++) {
                    const float gc = alpha64(m) * cos64(m * t);
                    const float gs = alpha64(m) * cos64(m * t + 16);
                    if (gc != 0.0f) {
                        C0 = fmaf(yRL[m], gc, C0);
                        C1 = fmaf(yRH[m], gc, C1);
                    }
                    if (gs != 0.0f) {
                        S0 = fmaf(yIL[m], gs, S0);
                        S1 = fmaf(yIH[m], gs, S1);
                    }
                }
                outp[(long)t * (SCOL / 2)]        = pack2(C0 + S0, C1 + S1);
                outp[(long)(64 - t) * (SCOL / 2)] = pack2(C0 - S0, C1 - S1);
            }
        }
    }
}

// =====================================================================
extern "C" void kernel_launch(void* const* d_in, const int* in_sizes, int n_in,
                              void* d_out, int out_size) {
    const float* x = (const float*)d_in[0];   // [64][1024][16][64] f32
    const float* w = (const float*)d_in[1];   // [64][64][16][2] f32
    float* out     = (float*)d_out;           // [64][1024][16][64] f32
    (void)in_sizes; (void)n_in; (void)out_size;

    cudaFuncSetAttribute(fused_spectral, cudaFuncAttributeMaxDynamicSharedMemorySize, 196608);

    w_pack<<<128, 256>>>(w);
    fused_spectral<<<NBLK, NTHR, 196608>>>(x, out);
}